// round 16
// baseline (speedup 1.0000x reference)
#include <cuda_runtime.h>
#include <cuda_fp16.h>
#include <math.h>
#include <stdint.h>

// ---------------- constants ----------------
#define DIMC   512
#define NHEAD  16
#define HD     32
#define SHIFT_ 4
#define ROWS   65536       // B * L
#define HID    2048
#define QKVC   1536

// ---------------- scratch ----------------
__device__ __half g_yw [ (size_t)ROWS * DIMC ];   // LN1 output, window order (fp16)
__device__ float  g_mw [ ROWS ];                  // clipped prior, window order
__device__ __half g_qkv[ (size_t)ROWS * QKVC ];   // qkv, window order (fp16)
__device__ __half g_ao [ (size_t)ROWS * DIMC ];   // attention output, window order (fp16)
__device__ __half g_x1 [ (size_t)ROWS * DIMC ];   // shortcut + proj, (b,l) order (fp16)
__device__ __half g_ln2[ (size_t)ROWS * DIMC ];   // LN2 output, (b,l) order (fp16)
__device__ __half g_h  [ (size_t)ROWS * HID  ];   // fc1+gelu output (fp16)

// fp16 weight copies
__device__ __half g_qkvw_h [ QKVC * DIMC ];
__device__ __half g_projw_h[ DIMC * DIMC ];
__device__ __half g_fc1w_h [ HID  * DIMC ];
__device__ __half g_fc2w_h [ DIMC * HID  ];

// ---------------- helpers ----------------
__device__ __forceinline__ uint32_t smem_to_u32(const void* smem_ptr) {
    uint32_t addr;
    asm("{ .reg .u64 tmp; cvta.to.shared.u64 tmp, %1; cvt.u32.u64 %0, tmp; }"
        : "=r"(addr) : "l"(smem_ptr));
    return addr;
}

#define CP_ASYNC16(dst, src) \
    asm volatile("cp.async.cg.shared.global [%0], [%1], 16;" \
        :: "r"(dst), "l"(src) : "memory")
#define CP_COMMIT() asm volatile("cp.async.commit_group;" ::: "memory")
#define CP_WAIT(n)  asm volatile("cp.async.wait_group " #n ";" ::: "memory")

#define LDMX4(r0, r1, r2, r3, addr) \
    asm volatile("ldmatrix.sync.aligned.m8n8.x4.shared.b16 {%0,%1,%2,%3}, [%4];" \
        : "=r"(r0), "=r"(r1), "=r"(r2), "=r"(r3) : "r"(addr))

#define MMA16816(d, a, b0, b1) \
    asm volatile("mma.sync.aligned.m16n8k16.row.col.f32.f16.f16.f32 " \
        "{%0,%1,%2,%3}, {%4,%5,%6,%7}, {%8,%9}, {%0,%1,%2,%3};" \
        : "+f"((d)[0]), "+f"((d)[1]), "+f"((d)[2]), "+f"((d)[3]) \
        : "r"((a)[0]), "r"((a)[1]), "r"((a)[2]), "r"((a)[3]), "r"(b0), "r"(b1))

// ---------------- weights fp32 -> fp16 (single merged launch) ----------------
#define NW0 (QKVC * DIMC)
#define NW1 (DIMC * DIMC)
#define NW2 (HID * DIMC)
#define NW3 (DIMC * HID)
#define NWTOT (NW0 + NW1 + NW2 + NW3)

__global__ __launch_bounds__(256) void cvt_all_kernel(
    const float* __restrict__ s0, const float* __restrict__ s1,
    const float* __restrict__ s2, const float* __restrict__ s3,
    __half* __restrict__ d0, __half* __restrict__ d1,
    __half* __restrict__ d2, __half* __restrict__ d3)
{
    int i = (blockIdx.x * 256 + threadIdx.x) * 8;
    if (i >= NWTOT) return;
    const float* src; __half* dst; int off;
    if (i < NW0)                 { src = s0; dst = d0; off = i; }
    else if (i < NW0+NW1)        { src = s1; dst = d1; off = i - NW0; }
    else if (i < NW0+NW1+NW2)    { src = s2; dst = d2; off = i - NW0 - NW1; }
    else                         { src = s3; dst = d3; off = i - NW0 - NW1 - NW2; }
    float4 a = *(const float4*)(src + off);
    float4 b = *(const float4*)(src + off + 4);
    __half2* d = (__half2*)(dst + off);
    d[0] = __floats2half2_rn(a.x, a.y);
    d[1] = __floats2half2_rn(a.z, a.w);
    d[2] = __floats2half2_rn(b.x, b.y);
    d[3] = __floats2half2_rn(b.z, b.w);
}

// ---------------- LN1 + shift + window partition (fp16 out) ----------------
__global__ __launch_bounds__(256) void ln1_win_kernel(
    const float* __restrict__ x, const float* __restrict__ Mmap,
    const float* __restrict__ gamma, const float* __restrict__ beta)
{
    int warp = threadIdx.x >> 5, lane = threadIdx.x & 31;
    int row  = (blockIdx.x << 3) + warp;
    int bq   = row >> 12, local = row & 4095;
    int wloc = local >> 6, t = local & 63;
    int hh = (((wloc >> 3) << 3) + (t >> 3) + SHIFT_) & 63;
    int ww = (((wloc &  7) << 3) + (t &  7) + SHIFT_) & 63;
    size_t src = ((size_t)bq * 4096 + (size_t)hh * 64 + ww) * DIMC;

    const float4* xp = (const float4*)(x + src);
    float v[16];
    float s = 0.f, ss = 0.f;
#pragma unroll
    for (int i = 0; i < 4; i++) {
        float4 f = xp[i * 32 + lane];
        v[i*4+0]=f.x; v[i*4+1]=f.y; v[i*4+2]=f.z; v[i*4+3]=f.w;
        s  += f.x + f.y + f.z + f.w;
        ss += f.x*f.x + f.y*f.y + f.z*f.z + f.w*f.w;
    }
#pragma unroll
    for (int o = 16; o; o >>= 1) {
        s  += __shfl_xor_sync(0xffffffffu, s,  o);
        ss += __shfl_xor_sync(0xffffffffu, ss, o);
    }
    float mean = s * (1.f/512.f);
    float var  = ss * (1.f/512.f) - mean * mean;
    float rstd = rsqrtf(var + 1e-5f);

    __half2* yp = (__half2*)(g_yw + (size_t)row * DIMC);
    const float4* gp = (const float4*)gamma;
    const float4* bp = (const float4*)beta;
#pragma unroll
    for (int i = 0; i < 4; i++) {
        float4 g4 = gp[i*32+lane], b4 = bp[i*32+lane];
        float o0 = (v[i*4+0]-mean)*rstd*g4.x + b4.x;
        float o1 = (v[i*4+1]-mean)*rstd*g4.y + b4.y;
        float o2 = (v[i*4+2]-mean)*rstd*g4.z + b4.z;
        float o3 = (v[i*4+3]-mean)*rstd*g4.w + b4.w;
        yp[(i*32+lane)*2 + 0] = __floats2half2_rn(o0, o1);
        yp[(i*32+lane)*2 + 1] = __floats2half2_rn(o2, o3);
    }
    if (lane == 0) {
        float m = Mmap[(size_t)bq * 4096 + (size_t)hh * 64 + ww];
        g_mw[row] = fminf(fmaxf(m, 0.f), 1.f);
    }
}

// ---------------- LN2 (fp16 in, fp16 out) ----------------
__global__ __launch_bounds__(256) void ln2_kernel(
    const float* __restrict__ gamma, const float* __restrict__ beta)
{
    int warp = threadIdx.x >> 5, lane = threadIdx.x & 31;
    int row  = (blockIdx.x << 3) + warp;

    const uint4* xp = (const uint4*)(g_x1 + (size_t)row * DIMC);
    float v[16];
    float s = 0.f, ss = 0.f;
#pragma unroll
    for (int i = 0; i < 2; i++) {
        uint4 u = xp[i * 32 + lane];
        const __half2* hp = (const __half2*)&u;
#pragma unroll
        for (int j = 0; j < 4; j++) {
            float2 f = __half22float2(hp[j]);
            v[i*8 + j*2]     = f.x;
            v[i*8 + j*2 + 1] = f.y;
            s += f.x + f.y;
            ss += f.x*f.x + f.y*f.y;
        }
    }
#pragma unroll
    for (int o = 16; o; o >>= 1) {
        s  += __shfl_xor_sync(0xffffffffu, s,  o);
        ss += __shfl_xor_sync(0xffffffffu, ss, o);
    }
    float mean = s * (1.f/512.f);
    float var  = ss * (1.f/512.f) - mean * mean;
    float rstd = rsqrtf(var + 1e-5f);

    __half* yp = g_ln2 + (size_t)row * DIMC;
#pragma unroll
    for (int i = 0; i < 2; i++) {
        int c0 = (i * 32 + lane) * 8;
        float4 g0 = *(const float4*)(gamma + c0);
        float4 g1 = *(const float4*)(gamma + c0 + 4);
        float4 b0 = *(const float4*)(beta + c0);
        float4 b1 = *(const float4*)(beta + c0 + 4);
        __half2 o2[4];
        o2[0] = __floats2half2_rn((v[i*8+0]-mean)*rstd*g0.x + b0.x,
                                  (v[i*8+1]-mean)*rstd*g0.y + b0.y);
        o2[1] = __floats2half2_rn((v[i*8+2]-mean)*rstd*g0.z + b0.z,
                                  (v[i*8+3]-mean)*rstd*g0.w + b0.w);
        o2[2] = __floats2half2_rn((v[i*8+4]-mean)*rstd*g1.x + b1.x,
                                  (v[i*8+5]-mean)*rstd*g1.y + b1.y);
        o2[3] = __floats2half2_rn((v[i*8+6]-mean)*rstd*g1.z + b1.z,
                                  (v[i*8+7]-mean)*rstd*g1.w + b1.w);
        *(uint4*)(yp + c0) = *(uint4*)o2;
    }
}

// ---------------- fp16 mma.sync GEMM: C(MxN) = A(MxK) * W(NxK)^T + bias ----------------
// Threadblock 128x128, K-chunk 64 halves, 16 warps (512 thr), warp tile 32x32.
// 3-stage cp.async pipeline, 2 CTAs/SM -> 32 warps/SM.
#define EPI_NONE 0
#define EPI_GELU 1
#define EPI_PROJ 2
#define EPI_RES  3

#define STAGE_BYTES 32768
#define GEMM_SMEM   (3 * STAGE_BYTES)   // 96KB; 2 CTAs = 192KB

// Load one 128x64-half tile into swizzled smem. 1024 16B-chunks over 512 threads.
__device__ __forceinline__ void load_tile_async(
    uint32_t sbase, const __half* __restrict__ G, int row0, int K, int k0, int t)
{
#pragma unroll
    for (int r = 0; r < 2; r++) {
        int ch = t + r * 512;
        int m  = ch >> 3;
        int c  = ch & 7;
        uint32_t dst = sbase + m * 128 + ((c ^ (m & 7)) << 4);
        const __half* src = G + (size_t)(row0 + m) * K + k0 + c * 8;
        CP_ASYNC16(dst, src);
    }
}

template<int EPI>
__global__ __launch_bounds__(512, 2) void mma_gemm(
    const __half* __restrict__ A, const __half* __restrict__ W,
    const float* __restrict__ bias, void* __restrict__ Cv,
    int M, int N, int K, const void* __restrict__ auxv)
{
    extern __shared__ float smf[];
    uint32_t sb = smem_to_u32(smf);
    int tid = threadIdx.x, wid = tid >> 5, lane = tid & 31;
    int m0 = blockIdx.y << 7, n0 = blockIdx.x << 7;
    int nc = K >> 6;

    float acc[2][4][4];
#pragma unroll
    for (int i = 0; i < 2; i++)
#pragma unroll
        for (int j = 0; j < 4; j++)
#pragma unroll
            for (int k = 0; k < 4; k++) acc[i][j][k] = 0.f;

    // prologue: chunks 0,1 -> stages 0,1
    load_tile_async(sb,                 A, m0, K, 0,  tid);
    load_tile_async(sb + 16384,         W, n0, K, 0,  tid);
    CP_COMMIT();
    load_tile_async(sb + STAGE_BYTES,         A, m0, K, 64, tid);
    load_tile_async(sb + STAGE_BYTES + 16384, W, n0, K, 64, tid);
    CP_COMMIT();

    const int wm = wid & 3, wn = wid >> 2;     // 4 x 32 M bands, 4 x 32 N bands
    const uint32_t aRow = (wm << 5) + (lane & 15);
    const uint32_t aHi  = lane >> 4;
    const uint32_t aXor = lane & 7;
    const uint32_t bMat = lane >> 3;
    const uint32_t bR   = lane & 7;
    const uint32_t bRowOff = ((bMat >> 1) << 3) + bR;
    const uint32_t bChunkLo = bMat & 1;

    for (int c = 0; c < nc; c++) {
        if (c + 1 < nc) { CP_WAIT(1); } else { CP_WAIT(0); }
        __syncthreads();
        if (c + 2 < nc) {
            uint32_t nb = sb + (uint32_t)((c + 2) % 3) * STAGE_BYTES;
            load_tile_async(nb,         A, m0, K, (c + 2) << 6, tid);
            load_tile_async(nb + 16384, W, n0, K, (c + 2) << 6, tid);
            CP_COMMIT();
        }

        uint32_t aB = sb + (uint32_t)(c % 3) * STAGE_BYTES;
        uint32_t bB = aB + 16384u;

#pragma unroll
        for (int ks = 0; ks < 4; ks++) {
            uint32_t a[2][4];
#pragma unroll
            for (int ma = 0; ma < 2; ma++) {
                uint32_t addr = aB + (aRow + ma * 16) * 128
                              + ((((ks << 1) + aHi) ^ aXor) << 4);
                LDMX4(a[ma][0], a[ma][1], a[ma][2], a[ma][3], addr);
            }
            uint32_t b[4][2];
#pragma unroll
            for (int p = 0; p < 2; p++) {
                uint32_t nrow = (wn << 5) + (p << 4) + bRowOff;
                uint32_t chunk = (ks << 1) + bChunkLo;
                uint32_t addr = bB + nrow * 128 + ((chunk ^ bR) << 4);
                LDMX4(b[p*2][0], b[p*2][1], b[p*2+1][0], b[p*2+1][1], addr);
            }
#pragma unroll
            for (int ma = 0; ma < 2; ma++)
#pragma unroll
                for (int na = 0; na < 4; na++)
                    MMA16816(acc[ma][na], a[ma], b[na][0], b[na][1]);
        }
        __syncthreads();
    }

    // ---------------- epilogue (from registers) ----------------
    const int rBase = m0 + (wm << 5) + (lane >> 2);
    const int cBase = n0 + (wn << 5) + ((lane & 3) << 1);

    float bv[4][2];
#pragma unroll
    for (int na = 0; na < 4; na++) {
        bv[na][0] = __ldg(&bias[cBase + na * 8]);
        bv[na][1] = __ldg(&bias[cBase + na * 8 + 1]);
    }

#pragma unroll
    for (int ma = 0; ma < 2; ma++) {
#pragma unroll
        for (int half = 0; half < 2; half++) {
            int m = rBase + ma * 16 + half * 8;
            size_t obase;
            if (EPI == EPI_PROJ) {
                int bq = m >> 12, local = m & 4095;
                int wloc = local >> 6, t = local & 63;
                int hh = (((wloc >> 3) << 3) + (t >> 3) + SHIFT_) & 63;
                int ww = (((wloc &  7) << 3) + (t &  7) + SHIFT_) & 63;
                obase = ((size_t)bq * 4096 + (size_t)hh * 64 + ww) * DIMC;
            } else {
                obase = (size_t)m * N;
            }
#pragma unroll
            for (int na = 0; na < 4; na++) {
                int col = cBase + na * 8;
                float v0 = acc[ma][na][half * 2 + 0] + bv[na][0];
                float v1 = acc[ma][na][half * 2 + 1] + bv[na][1];
                if (EPI == EPI_GELU) {
                    v0 = 0.5f * v0 * (1.f + erff(v0 * 0.70710678118654752f));
                    v1 = 0.5f * v1 * (1.f + erff(v1 * 0.70710678118654752f));
                }
                size_t o = obase + col;
                if (EPI == EPI_PROJ) {
                    // aux = x (fp32), out = g_x1 (fp16)
                    float2 r2 = *(const float2*)((const float*)auxv + o);
                    v0 += r2.x; v1 += r2.y;
                    *(__half2*)((__half*)Cv + o) = __floats2half2_rn(v0, v1);
                } else if (EPI == EPI_RES) {
                    // aux = g_x1 (fp16), out = d_out (fp32)
                    float2 rf = __half22float2(*(const __half2*)((const __half*)auxv + o));
                    v0 += rf.x; v1 += rf.y;
                    float2 o2; o2.x = v0; o2.y = v1;
                    *(float2*)((float*)Cv + o) = o2;
                } else {
                    *(__half2*)((__half*)Cv + o) = __floats2half2_rn(v0, v1);
                }
            }
        }
    }
}

// ---------------- tensor-core attention per (window, head) ----------------
__global__ __launch_bounds__(128) void attn_kernel(const float* __restrict__ rpb_table)
{
    __shared__ __half qs [64 * 72];
    __shared__ __half ks2[64 * 72];
    __shared__ __half vt [32 * 72];     // V^T: row d (32), cols j (64)
    __shared__ float rpb[225];
    __shared__ float mhalf[64];
    __shared__ int   rid[64];

    int w   = blockIdx.x >> 4;
    int h   = blockIdx.x & 15;
    int tid = threadIdx.x, lane = tid & 31, wi = tid >> 5;

    const __half* qbase = g_qkv + (size_t)w * 64 * QKVC + h * HD;

#pragma unroll
    for (int r = 0; r < 2; r++) {
        int ch = tid + r * 128;
        int row = ch >> 2, c = ch & 3;
        const __half* srow = qbase + (size_t)row * QKVC + c * 8;
        *(uint4*)(qs  + row * 72 + c * 8) = *(const uint4*)(srow);
        *(uint4*)(ks2 + row * 72 + c * 8) = *(const uint4*)(srow + 512);
    }
#pragma unroll
    for (int r = 0; r < 2; r++) {
        int ch = tid + r * 128;
        int row = ch >> 2, c = ch & 3;
        union { uint4 u; __half hv[8]; } U;
        U.u = *(const uint4*)(qbase + (size_t)row * QKVC + 1024 + c * 8);
#pragma unroll
        for (int d = 0; d < 8; d++) vt[(c * 8 + d) * 72 + row] = U.hv[d];
    }
    for (int e = tid; e < 225; e += 128) rpb[e] = rpb_table[e * NHEAD + h];
    if (tid < 64) {
        mhalf[tid] = 0.5f * g_mw[w * 64 + tid];
        int wloc = w & 63;
        int hr = ((wloc >> 3) << 3) + (tid >> 3);
        int wr = ((wloc & 7)  << 3) + (tid & 7);
        int rh = hr < 56 ? 0 : (hr < 60 ? 1 : 2);
        int rw = wr < 56 ? 0 : (wr < 60 ? 1 : 2);
        rid[tid] = rh * 3 + rw;
    }
    __syncthreads();

    uint32_t qb = smem_to_u32(qs), kb = smem_to_u32(ks2), vb = smem_to_u32(vt);
    const uint32_t row16 = lane & 15;
    const uint32_t hi    = lane >> 4;
    const uint32_t bMat = lane >> 3, bR = lane & 7;
    const uint32_t bRowOff = ((bMat >> 1) << 3) + bR;
    const uint32_t bCl = bMat & 1;

    float s[8][4];
#pragma unroll
    for (int i = 0; i < 8; i++)
#pragma unroll
        for (int k = 0; k < 4; k++) s[i][k] = 0.f;

#pragma unroll
    for (int kc = 0; kc < 2; kc++) {
        uint32_t aq[4];
        uint32_t aaddr = qb + (wi * 16 + row16) * 144 + ((kc * 2 + hi) << 4);
        LDMX4(aq[0], aq[1], aq[2], aq[3], aaddr);
#pragma unroll
        for (int np = 0; np < 4; np++) {
            uint32_t b0, b1, b2, b3;
            uint32_t baddr = kb + (np * 16 + bRowOff) * 144 + ((kc * 2 + bCl) << 4);
            LDMX4(b0, b1, b2, b3, baddr);
            MMA16816(s[np*2],   aq, b0, b1);
            MMA16816(s[np*2+1], aq, b2, b3);
        }
    }

    int r0 = wi * 16 + (lane >> 2), r1 = r0 + 8;
    float mi0 = mhalf[r0], mi1 = mhalf[r1];
    int rid0 = rid[r0], rid1 = rid[r1];
    int ii0 = r0 >> 3, ji0 = r0 & 7, ii1 = r1 >> 3, ji1 = r1 & 7;
    const float SC = 0.17677669529663687f;

    float mx0 = -1e30f, mx1 = -1e30f;
#pragma unroll
    for (int nt = 0; nt < 8; nt++) {
        int j0 = nt * 8 + ((lane & 3) << 1), j1 = j0 + 1;
        float mj0 = mhalf[j0], mj1 = mhalf[j1];
        int rj0 = rid[j0], rj1 = rid[j1];
        int jh0 = j0 >> 3, jl0 = j0 & 7, jh1 = j1 >> 3, jl1 = j1 & 7;
        s[nt][0] = s[nt][0] * SC + rpb[(ii0 - jh0 + 7) * 15 + (ji0 - jl0 + 7)] + mi0 + mj0
                   + (rid0 != rj0 ? -100.f : 0.f);
        s[nt][1] = s[nt][1] * SC + rpb[(ii0 - jh1 + 7) * 15 + (ji0 - jl1 + 7)] + mi0 + mj1
                   + (rid0 != rj1 ? -100.f : 0.f);
        s[nt][2] = s[nt][2] * SC + rpb[(ii1 - jh0 + 7) * 15 + (ji1 - jl0 + 7)] + mi1 + mj0
                   + (rid1 != rj0 ? -100.f : 0.f);
        s[nt][3] = s[nt][3] * SC + rpb[(ii1 - jh1 + 7) * 15 + (ji1 - jl1 + 7)] + mi1 + mj1
                   + (rid1 != rj1 ? -100.f : 0.f);
        mx0 = fmaxf(mx0, fmaxf(s[nt][0], s[nt][1]));
        mx1 = fmaxf(mx1, fmaxf(s[nt][2], s[nt][3]));
    }
    mx0 = fmaxf(mx0, __shfl_xor_sync(0xffffffffu, mx0, 1));
    mx0 = fmaxf(mx0, __shfl_xor_sync(0xffffffffu, mx0, 2));
    mx1 = fmaxf(mx1, __shfl_xor_sync(0xffffffffu, mx1, 1));
    mx1 = fmaxf(mx1, __shfl_xor_sync(0xffffffffu, mx1, 2));

    float sum0 = 0.f, sum1 = 0.f;
#pragma unroll
    for (int nt = 0; nt < 8; nt++) {
        s[nt][0] = __expf(s[nt][0] - mx0);
        s[nt][1] = __expf(s[nt][1] - mx0);
        s[nt][2] = __expf(s[nt][2] - mx1);
        s[nt][3] = __expf(s[nt][3] - mx1);
        sum0 += s[nt][0] + s[nt][1];
        sum1 += s[nt][2] + s[nt][3];
    }
    sum0 += __shfl_xor_sync(0xffffffffu, sum0, 1);
    sum0 += __shfl_xor_sync(0xffffffffu, sum0, 2);
    sum1 += __shfl_xor_sync(0xffffffffu, sum1, 1);
    sum1 += __shfl_xor_sync(0xffffffffu, sum1, 2);
    float inv0 = 1.f / sum0, inv1 = 1.f / sum1;

    uint32_t pa[4][4];
#pragma unroll
    for (int kt = 0; kt < 4; kt++) {
        __half2 t0 = __floats2half2_rn(s[2*kt][0] * inv0, s[2*kt][1] * inv0);
        __half2 t1 = __floats2half2_rn(s[2*kt][2] * inv1, s[2*kt][3] * inv1);
        __half2 t2 = __floats2half2_rn(s[2*kt+1][0] * inv0, s[2*kt+1][1] * inv0);
        __half2 t3 = __floats2half2_rn(s[2*kt+1][2] * inv1, s[2*kt+1][3] * inv1);
        pa[kt][0] = *(uint32_t*)&t0;
        pa[kt][1] = *(uint32_t*)&t1;
        pa[kt][2] = *(uint32_t*)&t2;
        pa[kt][3] = *(uint32_t*)&t3;
    }

    float o[4][4];
#pragma unroll
    for (int i = 0; i < 4; i++)
#pragma unroll
        for (int k = 0; k < 4; k++) o[i][k] = 0.f;

#pragma unroll
    for (int kt = 0; kt < 4; kt++) {
        uint32_t b0, b1, b2, b3;
        uint32_t addr0 = vb + (bRowOff) * 144 + ((kt * 2 + bCl) << 4);
        LDMX4(b0, b1, b2, b3, addr0);
        MMA16816(o[0], pa[kt], b0, b1);
        MMA16816(o[1], pa[kt], b2, b3);
        uint32_t addr1 = vb + (16 + bRowOff) * 144 + ((kt * 2 + bCl) << 4);
        LDMX4(b0, b1, b2, b3, addr1);
        MMA16816(o[2], pa[kt], b0, b1);
        MMA16816(o[3], pa[kt], b2, b3);
    }

    __half* dst = g_ao + (size_t)(w * 64) * DIMC + h * HD;
#pragma unroll
    for (int dt = 0; dt < 4; dt++) {
        int col = dt * 8 + ((lane & 3) << 1);
        *(__half2*)(dst + (size_t)r0 * DIMC + col) = __floats2half2_rn(o[dt][0], o[dt][1]);
        *(__half2*)(dst + (size_t)r1 * DIMC + col) = __floats2half2_rn(o[dt][2], o[dt][3]);
    }
}

// ---------------- launcher ----------------
extern "C" void kernel_launch(void* const* d_in, const int* in_sizes, int n_in,
                              void* d_out, int out_size)
{
    (void)in_sizes; (void)n_in; (void)out_size;
    const float* x       = (const float*)d_in[0];
    const float* M_map   = (const float*)d_in[1];
    const float* n1g     = (const float*)d_in[2];
    const float* n1b     = (const float*)d_in[3];
    const float* qkv_w   = (const float*)d_in[4];
    const float* qkv_b   = (const float*)d_in[5];
    const float* proj_w  = (const float*)d_in[6];
    const float* proj_b  = (const float*)d_in[7];
    const float* rpb_t   = (const float*)d_in[8];
    const float* n2g     = (const float*)d_in[9];
    const float* n2b     = (const float*)d_in[10];
    const float* fc1_w   = (const float*)d_in[11];
    const float* fc1_b   = (const float*)d_in[12];
    const float* fc2_w   = (const float*)d_in[13];
    const float* fc2_b   = (const float*)d_in[14];
    float* out = (float*)d_out;

    void *p_yw, *p_qkv, *p_ao, *p_x1, *p_ln2, *p_h;
    void *p_qkvw, *p_projw, *p_fc1w, *p_fc2w;
    cudaGetSymbolAddress(&p_yw,  g_yw);
    cudaGetSymbolAddress(&p_qkv, g_qkv);
    cudaGetSymbolAddress(&p_ao,  g_ao);
    cudaGetSymbolAddress(&p_x1,  g_x1);
    cudaGetSymbolAddress(&p_ln2, g_ln2);
    cudaGetSymbolAddress(&p_h,   g_h);
    cudaGetSymbolAddress(&p_qkvw,  g_qkvw_h);
    cudaGetSymbolAddress(&p_projw, g_projw_h);
    cudaGetSymbolAddress(&p_fc1w,  g_fc1w_h);
    cudaGetSymbolAddress(&p_fc2w,  g_fc2w_h);

    cudaFuncSetAttribute(mma_gemm<EPI_NONE>, cudaFuncAttributeMaxDynamicSharedMemorySize, GEMM_SMEM);
    cudaFuncSetAttribute(mma_gemm<EPI_GELU>, cudaFuncAttributeMaxDynamicSharedMemorySize, GEMM_SMEM);
    cudaFuncSetAttribute(mma_gemm<EPI_PROJ>, cudaFuncAttributeMaxDynamicSharedMemorySize, GEMM_SMEM);
    cudaFuncSetAttribute(mma_gemm<EPI_RES>,  cudaFuncAttributeMaxDynamicSharedMemorySize, GEMM_SMEM);

    // 0) weights fp32 -> fp16 (single launch)
    cvt_all_kernel<<<(NWTOT/8 + 255) / 256, 256>>>(
        qkv_w, proj_w, fc1_w, fc2_w,
        (__half*)p_qkvw, (__half*)p_projw, (__half*)p_fc1w, (__half*)p_fc2w);

    // 1) LN1 + shift + window partition (+ prior map)
    ln1_win_kernel<<<ROWS / 8, 256>>>(x, M_map, n1g, n1b);

    // 2) QKV GEMM
    mma_gemm<EPI_NONE><<<dim3(QKVC / 128, ROWS / 128), 512, GEMM_SMEM>>>(
        (const __half*)p_yw, (const __half*)p_qkvw, qkv_b, p_qkv, ROWS, QKVC, DIMC, nullptr);

    // 3) windowed attention (tensor-core)
    attn_kernel<<<1024 * NHEAD, 128>>>(rpb_t);

    // 4) proj GEMM + window-reverse + residual(x fp32) -> g_x1 (fp16)
    mma_gemm<EPI_PROJ><<<dim3(DIMC / 128, ROWS / 128), 512, GEMM_SMEM>>>(
        (const __half*)p_ao, (const __half*)p_projw, proj_b, p_x1, ROWS, DIMC, DIMC, x);

    // 5) LN2
    ln2_kernel<<<ROWS / 8, 256>>>(n2g, n2b);

    // 6) fc1 + GELU
    mma_gemm<EPI_GELU><<<dim3(HID / 128, ROWS / 128), 512, GEMM_SMEM>>>(
        (const __half*)p_ln2, (const __half*)p_fc1w, fc1_b, p_h, ROWS, HID, DIMC, nullptr);

    // 7) fc2 + residual(g_x1 fp16) -> d_out (fp32)
    mma_gemm<EPI_RES><<<dim3(DIMC / 128, ROWS / 128), 512, GEMM_SMEM>>>(
        (const __half*)p_h, (const __half*)p_fc2w, fc2_b, out, ROWS, DIMC, HID, p_x1);
}

// round 17
// speedup vs baseline: 1.1918x; 1.1918x over previous
#include <cuda_runtime.h>
#include <cuda_fp16.h>
#include <math.h>
#include <stdint.h>

// ---------------- constants ----------------
#define DIMC   512
#define NHEAD  16
#define HD     32
#define SHIFT_ 4
#define ROWS   65536       // B * L
#define HID    2048
#define QKVC   1536

// ---------------- scratch ----------------
__device__ __half g_yw [ (size_t)ROWS * DIMC ];   // LN1 output, window order (fp16)
__device__ float  g_mw [ ROWS ];                  // clipped prior, window order
__device__ __half g_qkv[ (size_t)ROWS * QKVC ];   // qkv, window order (fp16)
__device__ __half g_ao [ (size_t)ROWS * DIMC ];   // attention output, window order (fp16)
__device__ __half g_x1 [ (size_t)ROWS * DIMC ];   // shortcut + proj, (b,l) order (fp16)
__device__ __half g_ln2[ (size_t)ROWS * DIMC ];   // LN2 output, (b,l) order (fp16)
__device__ __half g_h  [ (size_t)ROWS * HID  ];   // fc1+gelu output (fp16)

// fp16 weight copies
__device__ __half g_qkvw_h [ QKVC * DIMC ];
__device__ __half g_projw_h[ DIMC * DIMC ];
__device__ __half g_fc1w_h [ HID  * DIMC ];
__device__ __half g_fc2w_h [ DIMC * HID  ];

// ---------------- helpers ----------------
__device__ __forceinline__ uint32_t smem_to_u32(const void* smem_ptr) {
    uint32_t addr;
    asm("{ .reg .u64 tmp; cvta.to.shared.u64 tmp, %1; cvt.u32.u64 %0, tmp; }"
        : "=r"(addr) : "l"(smem_ptr));
    return addr;
}

#define CP_ASYNC16(dst, src) \
    asm volatile("cp.async.cg.shared.global [%0], [%1], 16;" \
        :: "r"(dst), "l"(src) : "memory")
#define CP_COMMIT() asm volatile("cp.async.commit_group;" ::: "memory")
#define CP_WAIT(n)  asm volatile("cp.async.wait_group " #n ";" ::: "memory")

#define LDMX4(r0, r1, r2, r3, addr) \
    asm volatile("ldmatrix.sync.aligned.m8n8.x4.shared.b16 {%0,%1,%2,%3}, [%4];" \
        : "=r"(r0), "=r"(r1), "=r"(r2), "=r"(r3) : "r"(addr))

#define MMA16816(d, a, b0, b1) \
    asm volatile("mma.sync.aligned.m16n8k16.row.col.f32.f16.f16.f32 " \
        "{%0,%1,%2,%3}, {%4,%5,%6,%7}, {%8,%9}, {%0,%1,%2,%3};" \
        : "+f"((d)[0]), "+f"((d)[1]), "+f"((d)[2]), "+f"((d)[3]) \
        : "r"((a)[0]), "r"((a)[1]), "r"((a)[2]), "r"((a)[3]), "r"(b0), "r"(b1))

// ---------------- weights fp32 -> fp16 (single merged launch) ----------------
#define NW0 (QKVC * DIMC)
#define NW1 (DIMC * DIMC)
#define NW2 (HID * DIMC)
#define NW3 (DIMC * HID)
#define NWTOT (NW0 + NW1 + NW2 + NW3)

__global__ __launch_bounds__(256) void cvt_all_kernel(
    const float* __restrict__ s0, const float* __restrict__ s1,
    const float* __restrict__ s2, const float* __restrict__ s3,
    __half* __restrict__ d0, __half* __restrict__ d1,
    __half* __restrict__ d2, __half* __restrict__ d3)
{
    int i = (blockIdx.x * 256 + threadIdx.x) * 8;
    if (i >= NWTOT) return;
    const float* src; __half* dst; int off;
    if (i < NW0)                 { src = s0; dst = d0; off = i; }
    else if (i < NW0+NW1)        { src = s1; dst = d1; off = i - NW0; }
    else if (i < NW0+NW1+NW2)    { src = s2; dst = d2; off = i - NW0 - NW1; }
    else                         { src = s3; dst = d3; off = i - NW0 - NW1 - NW2; }
    float4 a = *(const float4*)(src + off);
    float4 b = *(const float4*)(src + off + 4);
    __half2* d = (__half2*)(dst + off);
    d[0] = __floats2half2_rn(a.x, a.y);
    d[1] = __floats2half2_rn(a.z, a.w);
    d[2] = __floats2half2_rn(b.x, b.y);
    d[3] = __floats2half2_rn(b.z, b.w);
}

// ---------------- LN1 + shift + window partition (fp16 out) ----------------
__global__ __launch_bounds__(256) void ln1_win_kernel(
    const float* __restrict__ x, const float* __restrict__ Mmap,
    const float* __restrict__ gamma, const float* __restrict__ beta)
{
    int warp = threadIdx.x >> 5, lane = threadIdx.x & 31;
    int row  = (blockIdx.x << 3) + warp;
    int bq   = row >> 12, local = row & 4095;
    int wloc = local >> 6, t = local & 63;
    int hh = (((wloc >> 3) << 3) + (t >> 3) + SHIFT_) & 63;
    int ww = (((wloc &  7) << 3) + (t &  7) + SHIFT_) & 63;
    size_t src = ((size_t)bq * 4096 + (size_t)hh * 64 + ww) * DIMC;

    const float4* xp = (const float4*)(x + src);
    float v[16];
    float s = 0.f, ss = 0.f;
#pragma unroll
    for (int i = 0; i < 4; i++) {
        float4 f = xp[i * 32 + lane];
        v[i*4+0]=f.x; v[i*4+1]=f.y; v[i*4+2]=f.z; v[i*4+3]=f.w;
        s  += f.x + f.y + f.z + f.w;
        ss += f.x*f.x + f.y*f.y + f.z*f.z + f.w*f.w;
    }
#pragma unroll
    for (int o = 16; o; o >>= 1) {
        s  += __shfl_xor_sync(0xffffffffu, s,  o);
        ss += __shfl_xor_sync(0xffffffffu, ss, o);
    }
    float mean = s * (1.f/512.f);
    float var  = ss * (1.f/512.f) - mean * mean;
    float rstd = rsqrtf(var + 1e-5f);

    __half2* yp = (__half2*)(g_yw + (size_t)row * DIMC);
    const float4* gp = (const float4*)gamma;
    const float4* bp = (const float4*)beta;
#pragma unroll
    for (int i = 0; i < 4; i++) {
        float4 g4 = gp[i*32+lane], b4 = bp[i*32+lane];
        float o0 = (v[i*4+0]-mean)*rstd*g4.x + b4.x;
        float o1 = (v[i*4+1]-mean)*rstd*g4.y + b4.y;
        float o2 = (v[i*4+2]-mean)*rstd*g4.z + b4.z;
        float o3 = (v[i*4+3]-mean)*rstd*g4.w + b4.w;
        yp[(i*32+lane)*2 + 0] = __floats2half2_rn(o0, o1);
        yp[(i*32+lane)*2 + 1] = __floats2half2_rn(o2, o3);
    }
    if (lane == 0) {
        float m = Mmap[(size_t)bq * 4096 + (size_t)hh * 64 + ww];
        g_mw[row] = fminf(fmaxf(m, 0.f), 1.f);
    }
}

// ---------------- LN2 (fp16 in, fp16 out) ----------------
__global__ __launch_bounds__(256) void ln2_kernel(
    const float* __restrict__ gamma, const float* __restrict__ beta)
{
    int warp = threadIdx.x >> 5, lane = threadIdx.x & 31;
    int row  = (blockIdx.x << 3) + warp;

    const uint4* xp = (const uint4*)(g_x1 + (size_t)row * DIMC);
    float v[16];
    float s = 0.f, ss = 0.f;
#pragma unroll
    for (int i = 0; i < 2; i++) {
        uint4 u = xp[i * 32 + lane];
        const __half2* hp = (const __half2*)&u;
#pragma unroll
        for (int j = 0; j < 4; j++) {
            float2 f = __half22float2(hp[j]);
            v[i*8 + j*2]     = f.x;
            v[i*8 + j*2 + 1] = f.y;
            s += f.x + f.y;
            ss += f.x*f.x + f.y*f.y;
        }
    }
#pragma unroll
    for (int o = 16; o; o >>= 1) {
        s  += __shfl_xor_sync(0xffffffffu, s,  o);
        ss += __shfl_xor_sync(0xffffffffu, ss, o);
    }
    float mean = s * (1.f/512.f);
    float var  = ss * (1.f/512.f) - mean * mean;
    float rstd = rsqrtf(var + 1e-5f);

    __half* yp = g_ln2 + (size_t)row * DIMC;
#pragma unroll
    for (int i = 0; i < 2; i++) {
        int c0 = (i * 32 + lane) * 8;
        float4 g0 = *(const float4*)(gamma + c0);
        float4 g1 = *(const float4*)(gamma + c0 + 4);
        float4 b0 = *(const float4*)(beta + c0);
        float4 b1 = *(const float4*)(beta + c0 + 4);
        __half2 o2[4];
        o2[0] = __floats2half2_rn((v[i*8+0]-mean)*rstd*g0.x + b0.x,
                                  (v[i*8+1]-mean)*rstd*g0.y + b0.y);
        o2[1] = __floats2half2_rn((v[i*8+2]-mean)*rstd*g0.z + b0.z,
                                  (v[i*8+3]-mean)*rstd*g0.w + b0.w);
        o2[2] = __floats2half2_rn((v[i*8+4]-mean)*rstd*g1.x + b1.x,
                                  (v[i*8+5]-mean)*rstd*g1.y + b1.y);
        o2[3] = __floats2half2_rn((v[i*8+6]-mean)*rstd*g1.z + b1.z,
                                  (v[i*8+7]-mean)*rstd*g1.w + b1.w);
        *(uint4*)(yp + c0) = *(uint4*)o2;
    }
}

// ---------------- fp16 mma.sync GEMM (R13-best config) ----------------
// Tile 128x128, K-chunk 64 halves, 8 warps, warp tile 64x32.
// 3-stage cp.async pipeline, single sync per chunk, frag double-buffering, 2 CTA/SM.
#define EPI_NONE 0
#define EPI_GELU 1
#define EPI_PROJ 2
#define EPI_RES  3

#define STAGE_BYTES 32768
#define GEMM_SMEM   (3 * STAGE_BYTES)

__device__ __forceinline__ void load_tile_async(
    uint32_t sbase, const __half* __restrict__ G, int row0, int K, int k0, int t)
{
#pragma unroll
    for (int r = 0; r < 4; r++) {
        int ch = t + r * 256;
        int m  = ch >> 3;
        int c  = ch & 7;
        uint32_t dst = sbase + m * 128 + ((c ^ (m & 7)) << 4);
        const __half* src = G + (size_t)(row0 + m) * K + k0 + c * 8;
        CP_ASYNC16(dst, src);
    }
}

struct Frag {
    uint32_t a[4][4];
    uint32_t b[4][2];
};

__device__ __forceinline__ void load_frag(
    Frag& f, int ks, uint32_t aB, uint32_t bB,
    uint32_t aRow, uint32_t aHi, uint32_t aXor,
    uint32_t wn, uint32_t bRowOff, uint32_t bChunkLo, uint32_t bR)
{
#pragma unroll
    for (int ma = 0; ma < 4; ma++) {
        uint32_t addr = aB + (aRow + ma * 16) * 128
                      + ((((ks << 1) + aHi) ^ aXor) << 4);
        LDMX4(f.a[ma][0], f.a[ma][1], f.a[ma][2], f.a[ma][3], addr);
    }
#pragma unroll
    for (int p = 0; p < 2; p++) {
        uint32_t nrow = (wn << 5) + (p << 4) + bRowOff;
        uint32_t chunk = (ks << 1) + bChunkLo;
        uint32_t addr = bB + nrow * 128 + ((chunk ^ bR) << 4);
        LDMX4(f.b[p*2][0], f.b[p*2][1], f.b[p*2+1][0], f.b[p*2+1][1], addr);
    }
}

__device__ __forceinline__ void do_mma(float acc[4][4][4], const Frag& f)
{
#pragma unroll
    for (int ma = 0; ma < 4; ma++)
#pragma unroll
        for (int na = 0; na < 4; na++)
            MMA16816(acc[ma][na], f.a[ma], f.b[na][0], f.b[na][1]);
}

template<int EPI>
__global__ __launch_bounds__(256, 2) void mma_gemm(
    const __half* __restrict__ A, const __half* __restrict__ W,
    const float* __restrict__ bias, void* __restrict__ Cv,
    int M, int N, int K, const void* __restrict__ auxv)
{
    extern __shared__ float smf[];
    uint32_t sb = smem_to_u32(smf);
    int tid = threadIdx.x, wid = tid >> 5, lane = tid & 31;
    int m0 = blockIdx.y << 7, n0 = blockIdx.x << 7;
    int nc = K >> 6;

    float acc[4][4][4];
#pragma unroll
    for (int i = 0; i < 4; i++)
#pragma unroll
        for (int j = 0; j < 4; j++)
#pragma unroll
            for (int k = 0; k < 4; k++) acc[i][j][k] = 0.f;

    load_tile_async(sb,                 A, m0, K, 0,  tid);
    load_tile_async(sb + 16384,         W, n0, K, 0,  tid);
    CP_COMMIT();
    load_tile_async(sb + STAGE_BYTES,         A, m0, K, 64, tid);
    load_tile_async(sb + STAGE_BYTES + 16384, W, n0, K, 64, tid);
    CP_COMMIT();

    const int wm = wid & 1, wn = wid >> 1;
    const uint32_t aRow = (wm << 6) + (lane & 15);
    const uint32_t aHi  = lane >> 4;
    const uint32_t aXor = lane & 7;
    const uint32_t bMat = lane >> 3;
    const uint32_t bR   = lane & 7;
    const uint32_t bRowOff = ((bMat >> 1) << 3) + bR;
    const uint32_t bChunkLo = bMat & 1;

    Frag f0, f1;

    for (int c = 0; c < nc; c++) {
        if (c + 1 < nc) { CP_WAIT(1); } else { CP_WAIT(0); }
        __syncthreads();
        if (c + 2 < nc) {
            uint32_t nb = sb + (uint32_t)((c + 2) % 3) * STAGE_BYTES;
            load_tile_async(nb,         A, m0, K, (c + 2) << 6, tid);
            load_tile_async(nb + 16384, W, n0, K, (c + 2) << 6, tid);
            CP_COMMIT();
        }

        uint32_t aB = sb + (uint32_t)(c % 3) * STAGE_BYTES;
        uint32_t bB = aB + 16384u;

        load_frag(f0, 0, aB, bB, aRow, aHi, aXor, (uint32_t)wn, bRowOff, bChunkLo, bR);
        load_frag(f1, 1, aB, bB, aRow, aHi, aXor, (uint32_t)wn, bRowOff, bChunkLo, bR);
        do_mma(acc, f0);
        load_frag(f0, 2, aB, bB, aRow, aHi, aXor, (uint32_t)wn, bRowOff, bChunkLo, bR);
        do_mma(acc, f1);
        load_frag(f1, 3, aB, bB, aRow, aHi, aXor, (uint32_t)wn, bRowOff, bChunkLo, bR);
        do_mma(acc, f0);
        do_mma(acc, f1);
    }

    const int rBase = m0 + (wm << 6) + (lane >> 2);
    const int cBase = n0 + (wn << 5) + ((lane & 3) << 1);

    float bv[4][2];
#pragma unroll
    for (int na = 0; na < 4; na++) {
        bv[na][0] = __ldg(&bias[cBase + na * 8]);
        bv[na][1] = __ldg(&bias[cBase + na * 8 + 1]);
    }

#pragma unroll
    for (int ma = 0; ma < 4; ma++) {
#pragma unroll
        for (int half = 0; half < 2; half++) {
            int m = rBase + ma * 16 + half * 8;
            size_t obase;
            if (EPI == EPI_PROJ) {
                int bq = m >> 12, local = m & 4095;
                int wloc = local >> 6, t = local & 63;
                int hh = (((wloc >> 3) << 3) + (t >> 3) + SHIFT_) & 63;
                int ww = (((wloc &  7) << 3) + (t &  7) + SHIFT_) & 63;
                obase = ((size_t)bq * 4096 + (size_t)hh * 64 + ww) * DIMC;
            } else {
                obase = (size_t)m * N;
            }
#pragma unroll
            for (int na = 0; na < 4; na++) {
                int col = cBase + na * 8;
                float v0 = acc[ma][na][half * 2 + 0] + bv[na][0];
                float v1 = acc[ma][na][half * 2 + 1] + bv[na][1];
                if (EPI == EPI_GELU) {
                    v0 = 0.5f * v0 * (1.f + erff(v0 * 0.70710678118654752f));
                    v1 = 0.5f * v1 * (1.f + erff(v1 * 0.70710678118654752f));
                }
                size_t o = obase + col;
                if (EPI == EPI_PROJ) {
                    // aux = x (fp32), out = g_x1 (fp16)
                    float2 r2 = *(const float2*)((const float*)auxv + o);
                    v0 += r2.x; v1 += r2.y;
                    *(__half2*)((__half*)Cv + o) = __floats2half2_rn(v0, v1);
                } else if (EPI == EPI_RES) {
                    // aux = g_x1 (fp16), out = d_out (fp32)
                    float2 rf = __half22float2(*(const __half2*)((const __half*)auxv + o));
                    v0 += rf.x; v1 += rf.y;
                    float2 o2; o2.x = v0; o2.y = v1;
                    *(float2*)((float*)Cv + o) = o2;
                } else {
                    *(__half2*)((__half*)Cv + o) = __floats2half2_rn(v0, v1);
                }
            }
        }
    }
}

// ---------------- tensor-core attention per (window, head) ----------------
__global__ __launch_bounds__(128) void attn_kernel(const float* __restrict__ rpb_table)
{
    __shared__ __half qs [64 * 72];
    __shared__ __half ks2[64 * 72];
    __shared__ __half vt [32 * 72];     // V^T: row d (32), cols j (64)
    __shared__ float rpb[225];
    __shared__ float mhalf[64];
    __shared__ int   rid[64];

    int w   = blockIdx.x >> 4;
    int h   = blockIdx.x & 15;
    int tid = threadIdx.x, lane = tid & 31, wi = tid >> 5;

    const __half* qbase = g_qkv + (size_t)w * 64 * QKVC + h * HD;

#pragma unroll
    for (int r = 0; r < 2; r++) {
        int ch = tid + r * 128;
        int row = ch >> 2, c = ch & 3;
        const __half* srow = qbase + (size_t)row * QKVC + c * 8;
        *(uint4*)(qs  + row * 72 + c * 8) = *(const uint4*)(srow);
        *(uint4*)(ks2 + row * 72 + c * 8) = *(const uint4*)(srow + 512);
    }
#pragma unroll
    for (int r = 0; r < 2; r++) {
        int ch = tid + r * 128;
        int row = ch >> 2, c = ch & 3;
        union { uint4 u; __half hv[8]; } U;
        U.u = *(const uint4*)(qbase + (size_t)row * QKVC + 1024 + c * 8);
#pragma unroll
        for (int d = 0; d < 8; d++) vt[(c * 8 + d) * 72 + row] = U.hv[d];
    }
    for (int e = tid; e < 225; e += 128) rpb[e] = rpb_table[e * NHEAD + h];
    if (tid < 64) {
        mhalf[tid] = 0.5f * g_mw[w * 64 + tid];
        int wloc = w & 63;
        int hr = ((wloc >> 3) << 3) + (tid >> 3);
        int wr = ((wloc & 7)  << 3) + (tid & 7);
        int rh = hr < 56 ? 0 : (hr < 60 ? 1 : 2);
        int rw = wr < 56 ? 0 : (wr < 60 ? 1 : 2);
        rid[tid] = rh * 3 + rw;
    }
    __syncthreads();

    uint32_t qb = smem_to_u32(qs), kb = smem_to_u32(ks2), vb = smem_to_u32(vt);
    const uint32_t row16 = lane & 15;
    const uint32_t hi    = lane >> 4;
    const uint32_t bMat = lane >> 3, bR = lane & 7;
    const uint32_t bRowOff = ((bMat >> 1) << 3) + bR;
    const uint32_t bCl = bMat & 1;

    float s[8][4];
#pragma unroll
    for (int i = 0; i < 8; i++)
#pragma unroll
        for (int k = 0; k < 4; k++) s[i][k] = 0.f;

#pragma unroll
    for (int kc = 0; kc < 2; kc++) {
        uint32_t aq[4];
        uint32_t aaddr = qb + (wi * 16 + row16) * 144 + ((kc * 2 + hi) << 4);
        LDMX4(aq[0], aq[1], aq[2], aq[3], aaddr);
#pragma unroll
        for (int np = 0; np < 4; np++) {
            uint32_t b0, b1, b2, b3;
            uint32_t baddr = kb + (np * 16 + bRowOff) * 144 + ((kc * 2 + bCl) << 4);
            LDMX4(b0, b1, b2, b3, baddr);
            MMA16816(s[np*2],   aq, b0, b1);
            MMA16816(s[np*2+1], aq, b2, b3);
        }
    }

    int r0 = wi * 16 + (lane >> 2), r1 = r0 + 8;
    float mi0 = mhalf[r0], mi1 = mhalf[r1];
    int rid0 = rid[r0], rid1 = rid[r1];
    int ii0 = r0 >> 3, ji0 = r0 & 7, ii1 = r1 >> 3, ji1 = r1 & 7;
    const float SC = 0.17677669529663687f;

    float mx0 = -1e30f, mx1 = -1e30f;
#pragma unroll
    for (int nt = 0; nt < 8; nt++) {
        int j0 = nt * 8 + ((lane & 3) << 1), j1 = j0 + 1;
        float mj0 = mhalf[j0], mj1 = mhalf[j1];
        int rj0 = rid[j0], rj1 = rid[j1];
        int jh0 = j0 >> 3, jl0 = j0 & 7, jh1 = j1 >> 3, jl1 = j1 & 7;
        s[nt][0] = s[nt][0] * SC + rpb[(ii0 - jh0 + 7) * 15 + (ji0 - jl0 + 7)] + mi0 + mj0
                   + (rid0 != rj0 ? -100.f : 0.f);
        s[nt][1] = s[nt][1] * SC + rpb[(ii0 - jh1 + 7) * 15 + (ji0 - jl1 + 7)] + mi0 + mj1
                   + (rid0 != rj1 ? -100.f : 0.f);
        s[nt][2] = s[nt][2] * SC + rpb[(ii1 - jh0 + 7) * 15 + (ji1 - jl0 + 7)] + mi1 + mj0
                   + (rid1 != rj0 ? -100.f : 0.f);
        s[nt][3] = s[nt][3] * SC + rpb[(ii1 - jh1 + 7) * 15 + (ji1 - jl1 + 7)] + mi1 + mj1
                   + (rid1 != rj1 ? -100.f : 0.f);
        mx0 = fmaxf(mx0, fmaxf(s[nt][0], s[nt][1]));
        mx1 = fmaxf(mx1, fmaxf(s[nt][2], s[nt][3]));
    }
    mx0 = fmaxf(mx0, __shfl_xor_sync(0xffffffffu, mx0, 1));
    mx0 = fmaxf(mx0, __shfl_xor_sync(0xffffffffu, mx0, 2));
    mx1 = fmaxf(mx1, __shfl_xor_sync(0xffffffffu, mx1, 1));
    mx1 = fmaxf(mx1, __shfl_xor_sync(0xffffffffu, mx1, 2));

    float sum0 = 0.f, sum1 = 0.f;
#pragma unroll
    for (int nt = 0; nt < 8; nt++) {
        s[nt][0] = __expf(s[nt][0] - mx0);
        s[nt][1] = __expf(s[nt][1] - mx0);
        s[nt][2] = __expf(s[nt][2] - mx1);
        s[nt][3] = __expf(s[nt][3] - mx1);
        sum0 += s[nt][0] + s[nt][1];
        sum1 += s[nt][2] + s[nt][3];
    }
    sum0 += __shfl_xor_sync(0xffffffffu, sum0, 1);
    sum0 += __shfl_xor_sync(0xffffffffu, sum0, 2);
    sum1 += __shfl_xor_sync(0xffffffffu, sum1, 1);
    sum1 += __shfl_xor_sync(0xffffffffu, sum1, 2);
    float inv0 = 1.f / sum0, inv1 = 1.f / sum1;

    uint32_t pa[4][4];
#pragma unroll
    for (int kt = 0; kt < 4; kt++) {
        __half2 t0 = __floats2half2_rn(s[2*kt][0] * inv0, s[2*kt][1] * inv0);
        __half2 t1 = __floats2half2_rn(s[2*kt][2] * inv1, s[2*kt][3] * inv1);
        __half2 t2 = __floats2half2_rn(s[2*kt+1][0] * inv0, s[2*kt+1][1] * inv0);
        __half2 t3 = __floats2half2_rn(s[2*kt+1][2] * inv1, s[2*kt+1][3] * inv1);
        pa[kt][0] = *(uint32_t*)&t0;
        pa[kt][1] = *(uint32_t*)&t1;
        pa[kt][2] = *(uint32_t*)&t2;
        pa[kt][3] = *(uint32_t*)&t3;
    }

    float o[4][4];
#pragma unroll
    for (int i = 0; i < 4; i++)
#pragma unroll
        for (int k = 0; k < 4; k++) o[i][k] = 0.f;

#pragma unroll
    for (int kt = 0; kt < 4; kt++) {
        uint32_t b0, b1, b2, b3;
        uint32_t addr0 = vb + (bRowOff) * 144 + ((kt * 2 + bCl) << 4);
        LDMX4(b0, b1, b2, b3, addr0);
        MMA16816(o[0], pa[kt], b0, b1);
        MMA16816(o[1], pa[kt], b2, b3);
        uint32_t addr1 = vb + (16 + bRowOff) * 144 + ((kt * 2 + bCl) << 4);
        LDMX4(b0, b1, b2, b3, addr1);
        MMA16816(o[2], pa[kt], b0, b1);
        MMA16816(o[3], pa[kt], b2, b3);
    }

    __half* dst = g_ao + (size_t)(w * 64) * DIMC + h * HD;
#pragma unroll
    for (int dt = 0; dt < 4; dt++) {
        int col = dt * 8 + ((lane & 3) << 1);
        *(__half2*)(dst + (size_t)r0 * DIMC + col) = __floats2half2_rn(o[dt][0], o[dt][1]);
        *(__half2*)(dst + (size_t)r1 * DIMC + col) = __floats2half2_rn(o[dt][2], o[dt][3]);
    }
}

// ---------------- launcher ----------------
extern "C" void kernel_launch(void* const* d_in, const int* in_sizes, int n_in,
                              void* d_out, int out_size)
{
    (void)in_sizes; (void)n_in; (void)out_size;
    const float* x       = (const float*)d_in[0];
    const float* M_map   = (const float*)d_in[1];
    const float* n1g     = (const float*)d_in[2];
    const float* n1b     = (const float*)d_in[3];
    const float* qkv_w   = (const float*)d_in[4];
    const float* qkv_b   = (const float*)d_in[5];
    const float* proj_w  = (const float*)d_in[6];
    const float* proj_b  = (const float*)d_in[7];
    const float* rpb_t   = (const float*)d_in[8];
    const float* n2g     = (const float*)d_in[9];
    const float* n2b     = (const float*)d_in[10];
    const float* fc1_w   = (const float*)d_in[11];
    const float* fc1_b   = (const float*)d_in[12];
    const float* fc2_w   = (const float*)d_in[13];
    const float* fc2_b   = (const float*)d_in[14];
    float* out = (float*)d_out;

    void *p_yw, *p_qkv, *p_ao, *p_x1, *p_ln2, *p_h;
    void *p_qkvw, *p_projw, *p_fc1w, *p_fc2w;
    cudaGetSymbolAddress(&p_yw,  g_yw);
    cudaGetSymbolAddress(&p_qkv, g_qkv);
    cudaGetSymbolAddress(&p_ao,  g_ao);
    cudaGetSymbolAddress(&p_x1,  g_x1);
    cudaGetSymbolAddress(&p_ln2, g_ln2);
    cudaGetSymbolAddress(&p_h,   g_h);
    cudaGetSymbolAddress(&p_qkvw,  g_qkvw_h);
    cudaGetSymbolAddress(&p_projw, g_projw_h);
    cudaGetSymbolAddress(&p_fc1w,  g_fc1w_h);
    cudaGetSymbolAddress(&p_fc2w,  g_fc2w_h);

    cudaFuncSetAttribute(mma_gemm<EPI_NONE>, cudaFuncAttributeMaxDynamicSharedMemorySize, GEMM_SMEM);
    cudaFuncSetAttribute(mma_gemm<EPI_GELU>, cudaFuncAttributeMaxDynamicSharedMemorySize, GEMM_SMEM);
    cudaFuncSetAttribute(mma_gemm<EPI_PROJ>, cudaFuncAttributeMaxDynamicSharedMemorySize, GEMM_SMEM);
    cudaFuncSetAttribute(mma_gemm<EPI_RES>,  cudaFuncAttributeMaxDynamicSharedMemorySize, GEMM_SMEM);

    // 0) weights fp32 -> fp16 (single launch)
    cvt_all_kernel<<<(NWTOT/8 + 255) / 256, 256>>>(
        qkv_w, proj_w, fc1_w, fc2_w,
        (__half*)p_qkvw, (__half*)p_projw, (__half*)p_fc1w, (__half*)p_fc2w);

    // 1) LN1 + shift + window partition (+ prior map)
    ln1_win_kernel<<<ROWS / 8, 256>>>(x, M_map, n1g, n1b);

    // 2) QKV GEMM
    mma_gemm<EPI_NONE><<<dim3(QKVC / 128, ROWS / 128), 256, GEMM_SMEM>>>(
        (const __half*)p_yw, (const __half*)p_qkvw, qkv_b, p_qkv, ROWS, QKVC, DIMC, nullptr);

    // 3) windowed attention (tensor-core)
    attn_kernel<<<1024 * NHEAD, 128>>>(rpb_t);

    // 4) proj GEMM + window-reverse + residual(x fp32) -> g_x1 (fp16)
    mma_gemm<EPI_PROJ><<<dim3(DIMC / 128, ROWS / 128), 256, GEMM_SMEM>>>(
        (const __half*)p_ao, (const __half*)p_projw, proj_b, p_x1, ROWS, DIMC, DIMC, x);

    // 5) LN2
    ln2_kernel<<<ROWS / 8, 256>>>(n2g, n2b);

    // 6) fc1 + GELU
    mma_gemm<EPI_GELU><<<dim3(HID / 128, ROWS / 128), 256, GEMM_SMEM>>>(
        (const __half*)p_ln2, (const __half*)p_fc1w, fc1_b, p_h, ROWS, HID, DIMC, nullptr);

    // 7) fc2 + residual(g_x1 fp16) -> d_out (fp32)
    mma_gemm<EPI_RES><<<dim3(DIMC / 128, ROWS / 128), 256, GEMM_SMEM>>>(
        (const __half*)p_h, (const __half*)p_fc2w, fc2_b, out, ROWS, DIMC, HID, p_x1);
}